// round 2
// baseline (speedup 1.0000x reference)
#include <cuda_runtime.h>
#include <cuda_bf16.h>
#include <cstdint>

// problem constants
#define CC   96
#define HQ   48
#define LL   2304            // 48*48
#define NBQ  64              // 4 quads * 16 batch
#define PXQ  36864           // 16*2304 pixels per quadrant
#define KD   4
#define NS   8
#define RD   6
#define XDW  24              // padded record: dts[6],pad[2],B[8],C[8]

// ---------------- static scratch ----------------
__device__ float g_hln [NBQ*LL*CC];
__device__ float g_a   [NBQ*LL*CC];
__device__ float g_zin [NBQ*LL*CC];
__device__ float g_vf  [NBQ*LL*CC];
__device__ float g_vt  [NBQ*LL*CC];
__device__ float g_xdbl[NBQ*KD*LL*XDW];
__device__ float g_ys  [NBQ*KD*LL*CC];
__device__ float g_y   [NBQ*LL*CC];
__device__ float g_ysum[NBQ*CC];
__device__ float g_att [NBQ*CC];

__device__ __forceinline__ float siluf(float v){ return v * (1.f/(1.f+__expf(-v))); }

__device__ __forceinline__ void fma2(unsigned long long &acc, unsigned long long a, unsigned long long b){
    asm("fma.rn.f32x2 %0,%1,%2,%0;" : "+l"(acc) : "l"(a), "l"(b));
}
__device__ __forceinline__ unsigned long long pack2(float v){
    unsigned long long r; asm("mov.b64 %0,{%1,%1};" : "=l"(r) : "f"(v)); return r;
}
__device__ __forceinline__ float2 unpack2(unsigned long long v){
    float2 r; asm("mov.b64 {%0,%1},%2;" : "=f"(r.x), "=f"(r.y) : "l"(v)); return r;
}
__device__ __forceinline__ void cpasync16(void* dst, const void* src){
    unsigned d = (unsigned)__cvta_generic_to_shared(dst);
    asm volatile("cp.async.ca.shared.global [%0],[%1],16;" :: "r"(d), "l"(src));
}

// =============== K0: channel LN of x -> g_hln (pixel-major) ===============
__global__ __launch_bounds__(256) void k0_ln(const float* __restrict__ x,
                                             const float* __restrict__ lg,
                                             const float* __restrict__ lb)
{
    __shared__ float tile[96*49];
    __shared__ float mu_s[48], rs_s[48];
    int qb = blockIdx.x, q = qb>>4, bb = qb&15, hr = blockIdx.y;
    if (blockIdx.x==0 && blockIdx.y==0)
        for (int i=threadIdx.x; i<NBQ*CC; i+=256) g_ysum[i]=0.f;
    int qh=(q>>1)*48, qw=(q&1)*48;
    const float* xb = x + (size_t)bb*96*96*96 + (size_t)(qh+hr)*96 + qw;
    for (int i=threadIdx.x; i<96*48; i+=256){
        int c=i/48, w=i%48;
        tile[c*49+w] = xb[(size_t)c*9216 + w];
    }
    __syncthreads();
    if (threadIdx.x < 48){
        int w=threadIdx.x; float s=0.f, ss=0.f;
        #pragma unroll 8
        for (int c=0;c<96;c++){ float v=tile[c*49+w]; s+=v; ss+=v*v; }
        float m=s*(1.f/96.f); float var=ss*(1.f/96.f)-m*m;
        mu_s[w]=m; rs_s[w]=rsqrtf(var+1e-6f);
    }
    __syncthreads();
    const float* gg=lg+q*96; const float* bv=lb+q*96;
    float* out = g_hln + ((size_t)qb*LL + hr*48)*96;
    for (int i=threadIdx.x; i<48*96; i+=256){
        int w=i/96, c=i%96;
        out[i] = (tile[c*49+w]-mu_s[w])*rs_s[w]*gg[c] + bv[c];
    }
}

// =============== K1: two 1x1 convs (GEMM, FFMA2) ===============
// grid (576 ptiles, 2 convs, 4 quads), block 256
__global__ __launch_bounds__(256) void k1_gemm(const float* __restrict__ p1w, const float* __restrict__ p1b,
                                               const float* __restrict__ p2w, const float* __restrict__ p2b)
{
    extern __shared__ char smem[];
    float* Xs = (float*)smem;                                  // [96][68]
    unsigned long long* Ws2 = (unsigned long long*)(smem + 96*68*4); // [96][96] packed
    int q = blockIdx.z, conv = blockIdx.y, P0 = blockIdx.x*64;
    const float* W    = (conv ? p2w : p1w) + q*96*96;
    const float* bias = (conv ? p2b : p1b) + q*96;
    const float* base = g_hln + ((size_t)q*PXQ + P0)*96;
    for (int i=threadIdx.x; i<64*96; i+=256){ int p=i/96, c=i%96; Xs[c*68+p]=base[i]; }
    for (int i=threadIdx.x; i<96*96; i+=256){ int d=i/96, k=i%96; Ws2[k*96+d]=pack2(W[i]); }
    __syncthreads();
    int tp = threadIdx.x & 15, tc = threadIdx.x >> 4;
    unsigned long long acc[6][2];
    #pragma unroll
    for (int j=0;j<6;j++){ acc[j][0]=0ull; acc[j][1]=0ull; }
    #pragma unroll 4
    for (int k=0;k<96;k++){
        ulonglong2 xv = *(const ulonglong2*)&Xs[k*68 + 4*tp];
        #pragma unroll
        for (int j=0;j<6;j++){
            unsigned long long wv = Ws2[k*96 + tc*6 + j];
            fma2(acc[j][0], xv.x, wv);
            fma2(acc[j][1], xv.y, wv);
        }
    }
    float* dst = conv ? g_zin : g_a;
    #pragma unroll
    for (int j=0;j<6;j++){
        int oc = tc*6+j;
        float bvl = bias[oc];
        float2 v0 = unpack2(acc[j][0]);
        float2 v1 = unpack2(acc[j][1]);
        float r0=v0.x+bvl, r1=v0.y+bvl, r2=v1.x+bvl, r3=v1.y+bvl;
        if (!conv){ r0=siluf(r0); r1=siluf(r1); r2=siluf(r2); r3=siluf(r3); }
        size_t ob = ((size_t)q*PXQ + P0 + 4*tp)*96 + oc;
        dst[ob      ] = r0;
        dst[ob + 96 ] = r1;
        dst[ob + 192] = r2;
        dst[ob + 288] = r3;
    }
}

// =============== K2: depthwise 3x3 + bias + silu + pre-transform ===============
__global__ __launch_bounds__(256) void k2_dw(const float* __restrict__ dww, const float* __restrict__ dwb,
                                             const int* __restrict__ bidx)
{
    extern __shared__ char smem[];
    float* rows = (float*)smem;             // [3][48*96]
    __shared__ float wsm[96*9];
    __shared__ float bsm[96];
    int qb = blockIdx.x, q = qb>>4, hr = blockIdx.y;
    for (int i=threadIdx.x; i<96*9; i+=256) wsm[i]=dww[q*96*9 + i];
    for (int i=threadIdx.x; i<96;   i+=256) bsm[i]=dwb[q*96 + i];
    for (int dy=0; dy<3; dy++){
        int hh = hr-1+dy;
        if (hh>=0 && hh<48){
            const float* src = g_zin + ((size_t)qb*LL + hh*48)*96;
            for (int i=threadIdx.x; i<48*96; i+=256) rows[dy*4608+i]=src[i];
        } else {
            for (int i=threadIdx.x; i<48*96; i+=256) rows[dy*4608+i]=0.f;
        }
    }
    __syncthreads();
    bool even = ((bidx[0] & 1) == 0);
    for (int i=threadIdx.x; i<48*96; i+=256){
        int w=i/96, c=i%96;
        float acc = bsm[c];
        #pragma unroll
        for (int dy=0; dy<3; dy++){
            #pragma unroll
            for (int dx=0; dx<3; dx++){
                int ww = w+dx-1;
                if (ww>=0 && ww<48) acc += wsm[c*9+dy*3+dx]*rows[dy*4608 + ww*96 + c];
            }
        }
        float z = siluf(acc);
        int pf, pt;
        if (even){ pf = w*48+hr;           pt = hr*48+w; }
        else     { pf = (47-hr)*48+(47-w); pt = (47-w)*48+(47-hr); }
        g_vf[((size_t)qb*LL + pf)*96 + c] = z;
        g_vt[((size_t)qb*LL + pt)*96 + c] = z;
    }
}

// =============== K3: x-projection GEMM (44 outputs/pixel/source) ===============
// grid (576 ptiles, 2 sources, 4 quads), block 256
__global__ __launch_bounds__(256) void k3_proj(const float* __restrict__ xprojw)
{
    extern __shared__ char smem[];
    float* Xs = (float*)smem;                                   // [96][68]
    unsigned long long* Ws2 = (unsigned long long*)(smem + 96*68*4); // [96][48]
    int q = blockIdx.z, src_t = blockIdx.y, P0 = blockIdx.x*64;
    int k0 = src_t;
    const float* base = (src_t ? g_vt : g_vf) + ((size_t)q*PXQ + P0)*96;
    for (int i=threadIdx.x; i<64*96; i+=256){ int p=i/96, c=i%96; Xs[c*68+p]=base[i]; }
    for (int i=threadIdx.x; i<48*96; i+=256){
        int oc=i/96, kk=i%96;
        float v=0.f;
        if (oc<44){
            int k = (oc<22)? k0 : k0+2;
            int d = (oc<22)? oc : oc-22;
            v = xprojw[(((size_t)q*4 + k)*22 + d)*96 + kk];
        }
        Ws2[kk*48+oc]=pack2(v);
    }
    __syncthreads();
    int tp = threadIdx.x & 15, tc = threadIdx.x >> 4;
    unsigned long long acc[3][2];
    #pragma unroll
    for (int j=0;j<3;j++){ acc[j][0]=0ull; acc[j][1]=0ull; }
    #pragma unroll 4
    for (int k=0;k<96;k++){
        ulonglong2 xv = *(const ulonglong2*)&Xs[k*68 + 4*tp];
        #pragma unroll
        for (int j=0;j<3;j++){
            unsigned long long wv = Ws2[k*48 + tc*3 + j];
            fma2(acc[j][0], xv.x, wv);
            fma2(acc[j][1], xv.y, wv);
        }
    }
    int b = P0 / LL;
    int l0 = P0 % LL + 4*tp;
    int qb = q*16 + b;
    #pragma unroll
    for (int j=0;j<3;j++){
        int oc = tc*3+j;
        if (oc>=44) continue;
        int k = (oc<22)? k0 : k0+2;
        int d = (oc<22)? oc : oc-22;
        int pos = (d<6)? d : d+2;
        float2 v0 = unpack2(acc[j][0]);
        float2 v1 = unpack2(acc[j][1]);
        size_t ob = (((size_t)qb*4 + k)*LL + l0)*XDW + pos;
        g_xdbl[ob        ] = v0.x;
        g_xdbl[ob + XDW  ] = v0.y;
        g_xdbl[ob + 2*XDW] = v1.x;
        g_xdbl[ob + 3*XDW] = v1.y;
    }
}

// =============== K-scan: selective scan, 1 thread per (q,b,k,c) lane ===============
// grid (64, 4), block 96
__global__ __launch_bounds__(96) void k_scan(const float* __restrict__ dtw_g, const float* __restrict__ dtb_g,
                                             const float* __restrict__ alog_g, const float* __restrict__ ds_g)
{
    __shared__ float s_u [2][16*96];
    __shared__ float s_xd[2][16*XDW];
    int qb = blockIdx.x, k = blockIdx.y, q = qb>>4;
    int c = threadIdx.x;
    int pidx = (q*4+k)*96 + c;
    float dtw[6];
    #pragma unroll
    for (int r=0;r<6;r++) dtw[r]=dtw_g[pidx*6+r];
    float dtb = dtb_g[pidx];
    float Ac[8];
    #pragma unroll
    for (int n=0;n<8;n++) Ac[n] = -__expf(alog_g[pidx*8+n]);
    float Dv = ds_g[pidx];
    const float* u_base  = ((k&1)? g_vt : g_vf) + (size_t)qb*LL*96;
    const float* xd_base = g_xdbl + ((size_t)qb*4+k)*LL*XDW;
    float* ys_base = g_ys + ((size_t)qb*4+k)*LL*96;
    bool rev = (k>=2);
    float hs[8];
    #pragma unroll
    for (int n=0;n<8;n++) hs[n]=0.f;

    // prefetch chunk 0
    {
        int sst = rev ? (LL-16) : 0;
        const float4* us = (const float4*)(u_base + (size_t)sst*96);
        #pragma unroll
        for (int j=0;j<4;j++) cpasync16(&s_u[0][(j*96+c)*4], &us[j*96+c]);
        cpasync16(&s_xd[0][c*4], (const float4*)(xd_base + (size_t)sst*XDW) + c);
        asm volatile("cp.async.commit_group;");
    }
    for (int cs=0; cs<144; cs++){
        if (cs<143){
            int cn = cs+1;
            int sst = rev ? (LL - 16*(cn+1)) : 16*cn;
            int buf = cn & 1;
            const float4* us = (const float4*)(u_base + (size_t)sst*96);
            #pragma unroll
            for (int j=0;j<4;j++) cpasync16(&s_u[buf][(j*96+c)*4], &us[j*96+c]);
            cpasync16(&s_xd[buf][c*4], (const float4*)(xd_base + (size_t)sst*XDW) + c);
            asm volatile("cp.async.commit_group;");
            asm volatile("cp.async.wait_group 1;");
        } else {
            asm volatile("cp.async.wait_group 0;");
        }
        __syncthreads();
        int buf = cs & 1;
        int sst = rev ? (LL - 16*(cs+1)) : 16*cs;
        #pragma unroll 4
        for (int j=0;j<16;j++){
            int off = rev ? (15-j) : j;
            const float* xd = &s_xd[buf][off*XDW];
            float4 d4 = *(const float4*)xd;
            float2 d2 = *(const float2*)(xd+4);
            float draw = dtb + dtw[0]*d4.x + dtw[1]*d4.y + dtw[2]*d4.z + dtw[3]*d4.w
                             + dtw[4]*d2.x + dtw[5]*d2.y;
            float delta = (draw > 15.f) ? draw : __logf(1.f + __expf(draw));
            float u = s_u[buf][off*96 + c];
            float du = delta*u;
            float4 B0 = *(const float4*)(xd+8);
            float4 B1 = *(const float4*)(xd+12);
            float4 C0 = *(const float4*)(xd+16);
            float4 C1 = *(const float4*)(xd+20);
            float y = Dv*u;
            hs[0] = __expf(delta*Ac[0])*hs[0] + du*B0.x;  y += hs[0]*C0.x;
            hs[1] = __expf(delta*Ac[1])*hs[1] + du*B0.y;  y += hs[1]*C0.y;
            hs[2] = __expf(delta*Ac[2])*hs[2] + du*B0.z;  y += hs[2]*C0.z;
            hs[3] = __expf(delta*Ac[3])*hs[3] + du*B0.w;  y += hs[3]*C0.w;
            hs[4] = __expf(delta*Ac[4])*hs[4] + du*B1.x;  y += hs[4]*C1.x;
            hs[5] = __expf(delta*Ac[5])*hs[5] + du*B1.y;  y += hs[5]*C1.y;
            hs[6] = __expf(delta*Ac[6])*hs[6] + du*B1.z;  y += hs[6]*C1.z;
            hs[7] = __expf(delta*Ac[7])*hs[7] + du*B1.w;  y += hs[7]*C1.w;
            ys_base[(size_t)(sst+off)*96 + c] = y;
        }
        __syncthreads();
    }
}

// =============== K4: combine 4 directions + ssln LN + p2n LN + a*z + ysum ===============
// grid (64, 48), block 96
__device__ __forceinline__ float2 blockReduce2(float a, float b, float2* red){
    #pragma unroll
    for (int o=16;o>0;o>>=1){
        a += __shfl_down_sync(0xffffffffu, a, o);
        b += __shfl_down_sync(0xffffffffu, b, o);
    }
    int wid = threadIdx.x>>5, lane = threadIdx.x&31;
    if (lane==0) red[wid]=make_float2(a,b);
    __syncthreads();
    float2 r = make_float2(red[0].x+red[1].x+red[2].x, red[0].y+red[1].y+red[2].y);
    __syncthreads();
    return r;
}

__global__ __launch_bounds__(96) void k4_comb(const float* __restrict__ g1g, const float* __restrict__ b1g,
                                              const float* __restrict__ g2g, const float* __restrict__ b2g,
                                              const int* __restrict__ bidx)
{
    __shared__ float2 red[3];
    int qb = blockIdx.x, q = qb>>4, hr = blockIdx.y, c = threadIdx.x;
    bool even = ((bidx[0] & 1) == 0);
    float g1=g1g[q*96+c], b1=b1g[q*96+c], g2=g2g[q*96+c], b2=b2g[q*96+c];
    size_t ysq = (size_t)qb*4;
    float ysum = 0.f;
    for (int w=0; w<48; w++){
        int lf = hr*48+w, lt = w*48+hr;
        float o = g_ys[((ysq+0)*LL+lf)*96+c] + g_ys[((ysq+2)*LL+lf)*96+c]
                + g_ys[((ysq+1)*LL+lt)*96+c] + g_ys[((ysq+3)*LL+lt)*96+c];
        float2 r = blockReduce2(o, o*o, red);
        float mu = r.x*(1.f/96.f);
        float rs = rsqrtf(r.y*(1.f/96.f) - mu*mu + 1e-6f);
        float t = (o-mu)*rs*g1 + b1;
        float2 r2 = blockReduce2(t, t*t, red);
        float mu2 = r2.x*(1.f/96.f);
        float rs2 = rsqrtf(r2.y*(1.f/96.f) - mu2*mu2 + 1e-6f);
        float z2 = (t-mu2)*rs2*g2 + b2;
        int po = even ? (w*48+hr) : ((47-hr)*48+(47-w));
        float a = g_a[((size_t)qb*LL + po)*96 + c];
        float y = a*z2;
        ysum += y;
        g_y[((size_t)qb*LL + po)*96 + c] = y;
    }
    atomicAdd(&g_ysum[qb*96+c], ysum);
}

// =============== K5: channel attention ===============
__global__ __launch_bounds__(96) void k5_att(const float* __restrict__ w1, const float* __restrict__ b1,
                                             const float* __restrict__ w2, const float* __restrict__ b2)
{
    __shared__ float sv[96], tv[12];
    int qb = blockIdx.x, q = qb>>4, c = threadIdx.x;
    sv[c] = g_ysum[qb*96+c] * (1.f/2304.f);
    __syncthreads();
    if (c<12){
        float acc = b1[q*12+c];
        #pragma unroll 8
        for (int cc=0; cc<96; cc++) acc += w1[(q*12+c)*96+cc]*sv[cc];
        tv[c] = siluf(acc);
    }
    __syncthreads();
    float acc = b2[q*96+c];
    #pragma unroll
    for (int r=0;r<12;r++) acc += w2[(q*96+c)*12+r]*tv[r];
    g_att[qb*96+c] = 1.f/(1.f+__expf(-acc));
}

// =============== K6: residual + att + transpose to NCHW ===============
__global__ __launch_bounds__(256) void k6_fin(const float* __restrict__ x, float* __restrict__ out)
{
    __shared__ float tile[96*49];
    __shared__ float atts[96];
    int qb = blockIdx.x, q = qb>>4, bb = qb&15, hr = blockIdx.y;
    int qh=(q>>1)*48, qw=(q&1)*48;
    const float* src = g_y + ((size_t)qb*LL + hr*48)*96;
    for (int i=threadIdx.x; i<48*96; i+=256){
        int w=i/96, c=i%96;
        tile[c*49+w] = src[i];
    }
    for (int i=threadIdx.x; i<96; i+=256) atts[i]=g_att[qb*96+i];
    __syncthreads();
    for (int i=threadIdx.x; i<96*48; i+=256){
        int c=i/48, w=i%48;
        size_t oi = ((size_t)(bb*96+c)*96 + qh+hr)*96 + qw + w;
        out[oi] = x[oi] + tile[c*49+w]*atts[c];
    }
}

// ================================================================
extern "C" void kernel_launch(void* const* d_in, const int* in_sizes, int n_in,
                              void* d_out, int out_size)
{
    const float* x    = (const float*)d_in[0];
    const float* ln_g = (const float*)d_in[1];
    const float* ln_b = (const float*)d_in[2];
    const float* p1w  = (const float*)d_in[3];
    const float* p1b  = (const float*)d_in[4];
    const float* p2w  = (const float*)d_in[5];
    const float* p2b  = (const float*)d_in[6];
    const float* dww  = (const float*)d_in[7];
    const float* dwb  = (const float*)d_in[8];
    const float* xprj = (const float*)d_in[9];
    const float* dtw  = (const float*)d_in[10];
    const float* dtb  = (const float*)d_in[11];
    const float* alog = (const float*)d_in[12];
    const float* dsv  = (const float*)d_in[13];
    const float* ssg  = (const float*)d_in[14];
    const float* ssb  = (const float*)d_in[15];
    const float* png  = (const float*)d_in[16];
    const float* pnb  = (const float*)d_in[17];
    const float* cw1  = (const float*)d_in[18];
    const float* cb1  = (const float*)d_in[19];
    const float* cw2  = (const float*)d_in[20];
    const float* cb2  = (const float*)d_in[21];
    const int*   bidx = (const int*)  d_in[22];
    float* out = (float*)d_out;

    const int smem_k1 = 96*68*4 + 96*96*8;   // 99840
    const int smem_k2 = 3*48*96*4;           // 55296
    const int smem_k3 = 96*68*4 + 48*96*8;   // 62976
    cudaFuncSetAttribute(k1_gemm, cudaFuncAttributeMaxDynamicSharedMemorySize, smem_k1);
    cudaFuncSetAttribute(k2_dw,   cudaFuncAttributeMaxDynamicSharedMemorySize, smem_k2);
    cudaFuncSetAttribute(k3_proj, cudaFuncAttributeMaxDynamicSharedMemorySize, smem_k3);

    k0_ln  <<<dim3(64,48), 256>>>(x, ln_g, ln_b);
    k1_gemm<<<dim3(576,2,4), 256, smem_k1>>>(p1w, p1b, p2w, p2b);
    k2_dw  <<<dim3(64,48), 256, smem_k2>>>(dww, dwb, bidx);
    k3_proj<<<dim3(576,2,4), 256, smem_k3>>>(xprj);
    k_scan <<<dim3(64,4), 96>>>(dtw, dtb, alog, dsv);
    k4_comb<<<dim3(64,48), 96>>>(ssg, ssb, png, pnb, bidx);
    k5_att <<<64, 96>>>(cw1, cb1, cw2, cb2);
    k6_fin <<<dim3(64,48), 256>>>(x, out);
}